// round 2
// baseline (speedup 1.0000x reference)
#include <cuda_runtime.h>
#include <math.h>

#define BB 256
#define SS 256
#define HH 512
#define INF 512
#define XROW 514   // IN + 2
#define NBLK 128   // persistent recurrence blocks (must all be co-resident; 128 <= 148 SMs)
#define HPB 4      // h-columns per recurrence block (NBLK*HPB == HH)

// Scratch (device globals; no runtime allocation allowed)
__device__ float g_G[(size_t)SS * 8 * BB * HH];   // [s][gate][b][h]  pre-activations
__device__ float g_hT[2][HH * BB];                // transposed hidden state [h][b], ping-pong
__device__ unsigned g_count;                      // grid-barrier monotonic counter

__device__ __forceinline__ float sigf(float x) { return 1.0f / (1.0f + expf(-x)); }

// ---- f32x2 packed-FMA helpers (ptxas never auto-fuses FFMA2) -------------
__device__ __forceinline__ unsigned long long pk2(float x, float y) {
    unsigned long long r;
    asm("mov.b64 %0, {%1, %2};" : "=l"(r) : "f"(x), "f"(y));
    return r;
}
__device__ __forceinline__ void fma2(unsigned long long& d, unsigned long long a,
                                     unsigned long long b) {
    asm("fma.rn.f32x2 %0, %1, %2, %0;" : "+l"(d) : "l"(a), "l"(b));
}
__device__ __forceinline__ float2 upk2(unsigned long long v) {
    float2 f;
    asm("mov.b64 {%0, %1}, %2;" : "=f"(f.x), "=f"(f.y) : "l"(v));
    return f;
}

struct ProjArgs {
    const float* x;          // lstm_input (B,S,514)
    const float* Wx[8];      // (512,512) each
    const float* bias[8];    // (512,)
    const float* aux1[8];    // Wt1/Wt2/Wd1/Wd2/Wto (512,) or null
    const float* aux2[8];    // Wdo for gate 7
};

// ---------------------------------------------------------------------------
// Projection GEMM: G[s][g][b][h] = x[b,s,:] @ Wx_g  + gate-specific extras
// grid = (N/64, M/64, 8 gates), block = 256 threads, 64x64 tile, f32x2 FMAs
// ---------------------------------------------------------------------------
__global__ void proj_kernel(ProjArgs p) {
    const int g  = blockIdx.z;
    const int m0 = blockIdx.y * 64;      // m = b*S + s
    const int n0 = blockIdx.x * 64;      // h

    __shared__ float As[64][17];                       // [m][k] padded
    __shared__ __align__(16) float Bs[16][64];         // [k][h]

    const int tid = threadIdx.x;
    const int tm = tid >> 4;             // 0..15
    const int tn = tid & 15;             // 0..15

    const float* W = p.Wx[g];

    unsigned long long acc2[4][2];
    #pragma unroll
    for (int i = 0; i < 4; i++) { acc2[i][0] = 0ULL; acc2[i][1] = 0ULL; }

    for (int k0 = 0; k0 < INF; k0 += 16) {
        #pragma unroll
        for (int q = 0; q < 4; q++) {
            int m = q * 16 + (tid >> 4);
            int kk = tid & 15;
            As[m][kk] = p.x[(size_t)(m0 + m) * XROW + 2 + k0 + kk];
        }
        {
            int idx = tid * 4;
            int kk = idx >> 6;
            int hc = idx & 63;
            float4 w = *(const float4*)&W[(size_t)(k0 + kk) * HH + n0 + hc];
            *(float4*)&Bs[kk][hc] = w;
        }
        __syncthreads();

        #pragma unroll
        for (int kk = 0; kk < 16; kk++) {
            ulonglong2 bq = *(const ulonglong2*)&Bs[kk][tn * 4];
            #pragma unroll
            for (int i = 0; i < 4; i++) {
                float a = As[tm * 4 + i][kk];
                unsigned long long a2 = pk2(a, a);
                fma2(acc2[i][0], a2, bq.x);
                fma2(acc2[i][1], a2, bq.y);
            }
        }
        __syncthreads();
    }

    const float* bias = p.bias[g];
    const float* a1p = p.aux1[g];
    const float* a2p = p.aux2[g];

    #pragma unroll
    for (int i = 0; i < 4; i++) {
        int m = m0 + tm * 4 + i;
        int bidx = m / SS;
        int sidx = m % SS;
        float Tt = p.x[(size_t)m * XROW + 0];
        float Dt = p.x[(size_t)m * XROW + 1];
        size_t base = (((size_t)sidx * 8 + g) * BB + bidx) * HH;
        float2 lo = upk2(acc2[i][0]);
        float2 hi = upk2(acc2[i][1]);
        float av[4] = {lo.x, lo.y, hi.x, hi.y};
        #pragma unroll
        for (int j = 0; j < 4; j++) {
            int h = n0 + tn * 4 + j;
            float v = av[j] + bias[h];
            if (g == 3 || g == 4)       v += sigf(Tt * a1p[h]);
            else if (g == 5 || g == 6)  v += sigf(Dt * a1p[h]);
            else if (g == 7)            v += Tt * a1p[h] + Dt * a2p[h];
            g_G[base + h] = v;
        }
    }
}

// ---------------------------------------------------------------------------
// Persistent recurrence kernel. 128 blocks x 256 threads. Block owns h-cols
// [h0, h0+4) for all 4 recurrent gates; weights live in SMEM for all steps;
// c state lives in registers (thread = batch row). Grid barrier per step.
// ---------------------------------------------------------------------------
__global__ void __launch_bounds__(256, 1)
rec_kernel(const float* __restrict__ Whi, const float* __restrict__ Whf,
           const float* __restrict__ Whc, const float* __restrict__ Who,
           float* __restrict__ out, unsigned long long out_size) {
    const int h0 = blockIdx.x * HPB;

    __shared__ __align__(16) float ws[HH][16];   // [k][gate*4 + j]  32 KB

    {
        const float* Wg[4] = {Whi, Whf, Whc, Who};
        for (int idx = threadIdx.x; idx < HH * 16; idx += 256) {
            int k = idx >> 4, cc = idx & 15, g = cc >> 2, j = cc & 3;
            ws[k][cc] = Wg[g][(size_t)k * HH + h0 + j];
        }
    }
    __syncthreads();

    const int b = threadIdx.x;           // 256 threads == BB
    float cst[4] = {0.f, 0.f, 0.f, 0.f};

    for (int t = 0; t < SS; t++) {
        const float* hT = g_hT[t & 1];
        float* hTn = g_hT[(t + 1) & 1];

        // Prefetch the 8 gate pre-activations (DRAM) — hidden under the GEMM
        size_t gbase = (size_t)t * 8 * (BB * HH) + (size_t)b * HH + h0;
        float4 Gv[8];
        #pragma unroll
        for (int g = 0; g < 8; g++)
            Gv[g] = __ldcg((const float4*)(g_G + gbase + (size_t)g * (BB * HH)));

        unsigned long long acc[8];
        #pragma unroll
        for (int i = 0; i < 8; i++) acc[i] = 0ULL;

        const float* hb = hT + b;
        #pragma unroll 1
        for (int k0 = 0; k0 < HH; k0 += 8) {
            #pragma unroll
            for (int u = 0; u < 8; u++) {
                int k = k0 + u;
                float a = __ldcg(hb + k * BB);   // bypass L1: written by other SMs
                unsigned long long a2 = pk2(a, a);
                const ulonglong2* wr = (const ulonglong2*)ws[k];
                ulonglong2 p0 = wr[0];
                ulonglong2 p1 = wr[1];
                fma2(acc[0], a2, p0.x); fma2(acc[1], a2, p0.y);
                fma2(acc[2], a2, p1.x); fma2(acc[3], a2, p1.y);
                ulonglong2 p2 = wr[2];
                ulonglong2 p3 = wr[3];
                fma2(acc[4], a2, p2.x); fma2(acc[5], a2, p2.y);
                fma2(acc[6], a2, p3.x); fma2(acc[7], a2, p3.y);
            }
        }

        float y[4][4];
        #pragma unroll
        for (int g = 0; g < 4; g++) {
            float2 lo = upk2(acc[g * 2]);
            float2 hi = upk2(acc[g * 2 + 1]);
            y[g][0] = lo.x; y[g][1] = lo.y; y[g][2] = hi.x; y[g][3] = hi.y;
        }

        float hn[4];
        #pragma unroll
        for (int j = 0; j < 4; j++) {
            float xi = ((const float*)&Gv[0])[j] + y[0][j];
            float xf = ((const float*)&Gv[1])[j] + y[1][j];
            float xc = ((const float*)&Gv[2])[j] + y[2][j];
            float t1 = ((const float*)&Gv[3])[j];
            float t2 = ((const float*)&Gv[4])[j];
            float d1 = ((const float*)&Gv[5])[j];
            float d2 = ((const float*)&Gv[6])[j];
            float o  = ((const float*)&Gv[7])[j] + y[3][j];

            float it = sigf(xi);
            float ft = sigf(xf);
            float jj = tanhf(xc);
            float T1 = sigf(t1), T2 = sigf(t2), D1 = sigf(d1), D2 = sigf(d2);
            float fc = ft * cst[j];
            float ij = it * jj;
            float chat = fc + ij * T1 * D1;
            float cnew = fc + ij * T2 * D2;
            float ot = sigf(o);
            hn[j] = ot * tanhf(chat);
            cst[j] = cnew;
            hTn[(h0 + j) * BB + b] = hn[j];
        }

        *(float4*)&out[((size_t)b * SS + t) * HH + h0] =
            make_float4(hn[0], hn[1], hn[2], hn[3]);

        if (t == SS - 1) {
            size_t base = (size_t)BB * SS * HH;
            #pragma unroll
            for (int j = 0; j < 4; j++) {
                size_t o1 = base + (size_t)b * HH + h0 + j;
                size_t o2 = base + (size_t)BB * HH + (size_t)b * HH + h0 + j;
                if (o1 < out_size) out[o1] = hn[j];
                if (o2 < out_size) out[o2] = cst[j];
            }
        } else {
            // grid barrier (all 128 blocks are co-resident by construction)
            __syncthreads();
            if (threadIdx.x == 0) {
                __threadfence();
                atomicAdd(&g_count, 1u);
                unsigned target = (unsigned)(t + 1) * (unsigned)NBLK;
                while (*(volatile unsigned*)&g_count < target) {
                    __nanosleep(32);
                }
                __threadfence();
            }
            __syncthreads();
        }
    }
}

__global__ void init_kernel() {
    int i = blockIdx.x * blockDim.x + threadIdx.x;
    if (i < BB * HH) {
        g_hT[0][i] = 0.0f;
    }
    if (i == 0) g_count = 0u;
}

extern "C" void kernel_launch(void* const* d_in, const int* in_sizes, int n_in,
                              void* d_out, int out_size) {
    const float* x = (const float*)d_in[0];

    ProjArgs pa = {};
    pa.x = x;
    pa.Wx[0] = (const float*)d_in[1];  pa.bias[0] = (const float*)d_in[3];
    pa.Wx[1] = (const float*)d_in[4];  pa.bias[1] = (const float*)d_in[6];
    pa.Wx[2] = (const float*)d_in[7];  pa.bias[2] = (const float*)d_in[9];
    pa.Wx[3] = (const float*)d_in[10]; pa.aux1[3] = (const float*)d_in[11]; pa.bias[3] = (const float*)d_in[12];
    pa.Wx[4] = (const float*)d_in[13]; pa.aux1[4] = (const float*)d_in[14]; pa.bias[4] = (const float*)d_in[15];
    pa.Wx[5] = (const float*)d_in[16]; pa.aux1[5] = (const float*)d_in[17]; pa.bias[5] = (const float*)d_in[18];
    pa.Wx[6] = (const float*)d_in[19]; pa.aux1[6] = (const float*)d_in[20]; pa.bias[6] = (const float*)d_in[21];
    pa.Wx[7] = (const float*)d_in[22]; pa.aux1[7] = (const float*)d_in[24]; pa.aux2[7] = (const float*)d_in[25];
    pa.bias[7] = (const float*)d_in[26];

    const float* Whi = (const float*)d_in[2];
    const float* Whf = (const float*)d_in[5];
    const float* Whc = (const float*)d_in[8];
    const float* Who = (const float*)d_in[23];

    float* out = (float*)d_out;

    init_kernel<<<(BB * HH + 255) / 256, 256>>>();

    dim3 pgrid(HH / 64, (BB * SS) / 64, 8);
    proj_kernel<<<pgrid, 256>>>(pa);

    rec_kernel<<<NBLK, 256>>>(Whi, Whf, Whc, Who, out,
                              (unsigned long long)out_size);
}

// round 3
// speedup vs baseline: 1.4704x; 1.4704x over previous
#include <cuda_runtime.h>
#include <math.h>

#define BB 256
#define SS 256
#define HH 512
#define INF 512
#define XROW 514   // IN + 2
#define NBLK 128   // persistent recurrence blocks (1/SM, co-resident)
#define KC 64      // k-chunk for staged h

// SMEM partition for rec kernel (dynamic): ws2 64KB | As 2x64KB | Gs 32KB
#define SM_WS2   0
#define SM_AS    65536
#define SM_GS    (65536 + 131072)
#define SM_TOTAL (65536 + 131072 + 32768)   // 229376

// Scratch (device globals; no runtime allocation allowed)
__device__ __align__(128) float g_G[(size_t)SS * 8 * BB * HH]; // [s][gate][b][h]
__device__ __align__(128) float g_hT[2][HH * BB];              // [h][b], ping-pong
__device__ unsigned g_count;

__device__ __forceinline__ float sigf(float x) { return 1.0f / (1.0f + expf(-x)); }

// ---- f32x2 packed-FMA helpers ----
__device__ __forceinline__ unsigned long long pk2(float x, float y) {
    unsigned long long r;
    asm("mov.b64 %0, {%1, %2};" : "=l"(r) : "f"(x), "f"(y));
    return r;
}
__device__ __forceinline__ void fma2(unsigned long long& d, unsigned long long a,
                                     unsigned long long b) {
    asm("fma.rn.f32x2 %0, %1, %2, %0;" : "+l"(d) : "l"(a), "l"(b));
}
__device__ __forceinline__ float2 upk2(unsigned long long v) {
    float2 f;
    asm("mov.b64 {%0, %1}, %2;" : "=f"(f.x), "=f"(f.y) : "l"(v));
    return f;
}

// ---- cp.async helpers (cg = L2-only, bypasses stale L1) ----
__device__ __forceinline__ void cpa16(void* dst_smem, const void* src) {
    unsigned d = (unsigned)__cvta_generic_to_shared(dst_smem);
    asm volatile("cp.async.cg.shared.global [%0], [%1], 16;" :: "r"(d), "l"(src));
}
#define CP_COMMIT() asm volatile("cp.async.commit_group;" ::: "memory")
#define CP_WAIT(n)  asm volatile("cp.async.wait_group %0;" :: "n"(n) : "memory")

struct ProjArgs {
    const float* x;
    const float* Wx[8];
    const float* bias[8];
    const float* aux1[8];
    const float* aux2[8];
};

// ---------------------------------------------------------------------------
// Projection GEMM (unchanged structure): G[s][g][b][h] = x @ Wx_g + extras
// ---------------------------------------------------------------------------
__global__ void proj_kernel(ProjArgs p) {
    const int g  = blockIdx.z;
    const int m0 = blockIdx.y * 64;
    const int n0 = blockIdx.x * 64;

    __shared__ float As[64][17];
    __shared__ __align__(16) float Bs[16][64];

    const int tid = threadIdx.x;
    const int tm = tid >> 4;
    const int tn = tid & 15;

    const float* W = p.Wx[g];

    unsigned long long acc2[4][2];
    #pragma unroll
    for (int i = 0; i < 4; i++) { acc2[i][0] = 0ULL; acc2[i][1] = 0ULL; }

    for (int k0 = 0; k0 < INF; k0 += 16) {
        #pragma unroll
        for (int q = 0; q < 4; q++) {
            int m = q * 16 + (tid >> 4);
            int kk = tid & 15;
            As[m][kk] = p.x[(size_t)(m0 + m) * XROW + 2 + k0 + kk];
        }
        {
            int idx = tid * 4;
            int kk = idx >> 6;
            int hc = idx & 63;
            float4 w = *(const float4*)&W[(size_t)(k0 + kk) * HH + n0 + hc];
            *(float4*)&Bs[kk][hc] = w;
        }
        __syncthreads();

        #pragma unroll
        for (int kk = 0; kk < 16; kk++) {
            ulonglong2 bq = *(const ulonglong2*)&Bs[kk][tn * 4];
            #pragma unroll
            for (int i = 0; i < 4; i++) {
                float a = As[tm * 4 + i][kk];
                unsigned long long a2 = pk2(a, a);
                fma2(acc2[i][0], a2, bq.x);
                fma2(acc2[i][1], a2, bq.y);
            }
        }
        __syncthreads();
    }

    const float* bias = p.bias[g];
    const float* a1p = p.aux1[g];
    const float* a2p = p.aux2[g];

    #pragma unroll
    for (int i = 0; i < 4; i++) {
        int m = m0 + tm * 4 + i;
        int bidx = m / SS;
        int sidx = m % SS;
        float Tt = p.x[(size_t)m * XROW + 0];
        float Dt = p.x[(size_t)m * XROW + 1];
        size_t base = (((size_t)sidx * 8 + g) * BB + bidx) * HH;
        float2 lo = upk2(acc2[i][0]);
        float2 hi = upk2(acc2[i][1]);
        float av[4] = {lo.x, lo.y, hi.x, hi.y};
        #pragma unroll
        for (int j = 0; j < 4; j++) {
            int h = n0 + tn * 4 + j;
            float v = av[j] + bias[h];
            if (g == 3 || g == 4)       v += sigf(Tt * a1p[h]);
            else if (g == 5 || g == 6)  v += sigf(Dt * a1p[h]);
            else if (g == 7)            v += Tt * a1p[h] + Dt * a2p[h];
            g_G[base + h] = v;
        }
    }
}

// ---------------------------------------------------------------------------
// Persistent recurrence. 128 blocks x 256 thr. Block owns h-cols [h0,h0+4)
// for all 4 recurrent gates. Thread: 4 batch rows x 1 h x 4 gates.
// Weights SMEM-resident (pre-duplicated f32x2 pairs); h staged via cp.async.
// ---------------------------------------------------------------------------
__global__ void __launch_bounds__(256, 1)
rec_kernel(const float* __restrict__ Whi, const float* __restrict__ Whf,
           const float* __restrict__ Whc, const float* __restrict__ Who,
           float* __restrict__ out, unsigned long long out_size) {
    extern __shared__ __align__(16) char smem_raw[];
    unsigned long long* ws2 = (unsigned long long*)(smem_raw + SM_WS2); // [k*16 + h*4 + g]
    float* Asmem = (float*)(smem_raw + SM_AS);                          // 2 x [KC][256]
    float* Gs    = (float*)(smem_raw + SM_GS);                          // [g][b][4h]

    const int tid = threadIdx.x;
    const int h0 = blockIdx.x * 4;
    const int hg = tid & 3;           // h within block
    const int rg = tid >> 2;          // row group (0..63)
    const int b0 = rg * 4;

    // Preload duplicated weight pairs: ws2[k][h][g] = (w,w)
    {
        const float* Wg[4] = {Whi, Whf, Whc, Who};
        for (int idx = tid; idx < HH * 16; idx += 256) {
            int k = idx >> 4, hc = (idx >> 2) & 3, g = idx & 3;
            float w = __ldg(&Wg[g][(size_t)k * HH + h0 + hc]);
            ws2[(size_t)k * 16 + hc * 4 + g] = pk2(w, w);
        }
    }
    __syncthreads();

    float cst[4] = {0.f, 0.f, 0.f, 0.f};

    for (int t = 0; t < SS; t++) {
        const float* hT = g_hT[t & 1];
        float* hTn = g_hT[(t + 1) & 1];

        // group 1: chunk 0 of h
        {
            const char* src = (const char*)hT;
            #pragma unroll
            for (int i = 0; i < 16; i++) {
                int off = (i * 256 + tid) * 16;
                cpa16((char*)Asmem + off, src + off);
            }
            CP_COMMIT();
        }
        // group 2: G slices [t][g][b=tid][h0..h0+3]
        {
            #pragma unroll
            for (int g = 0; g < 8; g++) {
                const float* src = g_G + (((size_t)t * 8 + g) * BB + tid) * HH + h0;
                cpa16(Gs + (g * 256 + tid) * 4, src);
            }
            CP_COMMIT();
        }

        unsigned long long acc[2][4];
        #pragma unroll
        for (int rp = 0; rp < 2; rp++)
            #pragma unroll
            for (int g = 0; g < 4; g++) acc[rp][g] = 0ULL;

        for (int c = 0; c < HH / KC; c++) {
            if (c < HH / KC - 1) {   // issue next chunk
                const char* src = (const char*)hT + (size_t)(c + 1) * KC * 256 * 4;
                char* dst = (char*)Asmem + ((c + 1) & 1) * (KC * 256 * 4);
                #pragma unroll
                for (int i = 0; i < 16; i++) {
                    int off = (i * 256 + tid) * 16;
                    cpa16(dst + off, src + off);
                }
                CP_COMMIT();
            }
            if (c == 0)                 CP_WAIT(2);
            else if (c < HH / KC - 1)   CP_WAIT(1);
            else                        CP_WAIT(0);
            __syncthreads();

            const float* A = Asmem + (c & 1) * (KC * 256) + b0;
            const unsigned long long* wp = ws2 + (size_t)c * KC * 16 + hg * 4;
            #pragma unroll 8
            for (int k = 0; k < KC; k++) {
                ulonglong2 aq  = *(const ulonglong2*)(A + k * 256);
                ulonglong2 w01 = *(const ulonglong2*)(wp + k * 16);
                ulonglong2 w23 = *(const ulonglong2*)(wp + k * 16 + 2);
                fma2(acc[0][0], aq.x, w01.x); fma2(acc[1][0], aq.y, w01.x);
                fma2(acc[0][1], aq.x, w01.y); fma2(acc[1][1], aq.y, w01.y);
                fma2(acc[0][2], aq.x, w23.x); fma2(acc[1][2], aq.y, w23.x);
                fma2(acc[0][3], aq.x, w23.y); fma2(acc[1][3], aq.y, w23.y);
            }
            __syncthreads();   // protect buffer before next-next issue
        }

        // Unpack: y[g][r] for rows b0+r
        float y[4][4];
        #pragma unroll
        for (int g = 0; g < 4; g++) {
            float2 lo = upk2(acc[0][g]);
            float2 hi = upk2(acc[1][g]);
            y[g][0] = lo.x; y[g][1] = lo.y; y[g][2] = hi.x; y[g][3] = hi.y;
        }

        float hn[4];
        #pragma unroll
        for (int r = 0; r < 4; r++) {
            int b = b0 + r;
            float xi = Gs[(0 * 256 + b) * 4 + hg] + y[0][r];
            float xf = Gs[(1 * 256 + b) * 4 + hg] + y[1][r];
            float xc = Gs[(2 * 256 + b) * 4 + hg] + y[2][r];
            float t1 = Gs[(3 * 256 + b) * 4 + hg];
            float t2 = Gs[(4 * 256 + b) * 4 + hg];
            float d1 = Gs[(5 * 256 + b) * 4 + hg];
            float d2 = Gs[(6 * 256 + b) * 4 + hg];
            float o  = Gs[(7 * 256 + b) * 4 + hg] + y[3][r];

            float it = sigf(xi);
            float ft = sigf(xf);
            float jj = tanhf(xc);
            float T1 = sigf(t1), T2 = sigf(t2), D1 = sigf(d1), D2 = sigf(d2);
            float fc = ft * cst[r];
            float ij = it * jj;
            float chat = fc + ij * T1 * D1;
            float cnew = fc + ij * T2 * D2;
            float ot = sigf(o);
            hn[r] = ot * tanhf(chat);
            cst[r] = cnew;
        }

        // next-step hidden state: [h][b] layout, float4 over b
        *(float4*)&hTn[(h0 + hg) * BB + b0] = make_float4(hn[0], hn[1], hn[2], hn[3]);

        // stage hn (and cst at the last step) into SMEM for coalesced STG
        float* hs = Asmem;            // reuse (As[0] idle: last compute used As[1])
        float* cs = Asmem + 4096;
        #pragma unroll
        for (int r = 0; r < 4; r++) hs[(b0 + r) * 4 + hg] = hn[r];
        if (t == SS - 1) {
            #pragma unroll
            for (int r = 0; r < 4; r++) cs[(b0 + r) * 4 + hg] = cst[r];
        }
        __syncthreads();
        {
            float4 v = *(const float4*)&hs[tid * 4];
            *(float4*)&out[((size_t)tid * SS + t) * HH + h0] = v;
            if (t == SS - 1) {
                unsigned long long base = (unsigned long long)BB * SS * HH;
                unsigned long long o1 = base + (unsigned long long)tid * HH + h0;
                unsigned long long o2 = o1 + (unsigned long long)BB * HH;
                if (o1 + 4 <= out_size) *(float4*)&out[o1] = v;
                if (o2 + 4 <= out_size) *(float4*)&out[o2] = *(const float4*)&cs[tid * 4];
            }
        }

        if (t < SS - 1) {
            // grid barrier (release h stores, acquire before next read)
            __threadfence();
            __syncthreads();
            if (tid == 0) {
                atomicAdd(&g_count, 1u);
                unsigned target = (unsigned)(t + 1) * (unsigned)NBLK;
                while (*(volatile unsigned*)&g_count < target) { __nanosleep(64); }
                __threadfence();
            }
            __syncthreads();
        }
    }
}

__global__ void init_kernel() {
    int i = blockIdx.x * blockDim.x + threadIdx.x;
    if (i < BB * HH) g_hT[0][i] = 0.0f;
    if (i == 0) g_count = 0u;
}

extern "C" void kernel_launch(void* const* d_in, const int* in_sizes, int n_in,
                              void* d_out, int out_size) {
    const float* x = (const float*)d_in[0];

    ProjArgs pa = {};
    pa.x = x;
    pa.Wx[0] = (const float*)d_in[1];  pa.bias[0] = (const float*)d_in[3];
    pa.Wx[1] = (const float*)d_in[4];  pa.bias[1] = (const float*)d_in[6];
    pa.Wx[2] = (const float*)d_in[7];  pa.bias[2] = (const float*)d_in[9];
    pa.Wx[3] = (const float*)d_in[10]; pa.aux1[3] = (const float*)d_in[11]; pa.bias[3] = (const float*)d_in[12];
    pa.Wx[4] = (const float*)d_in[13]; pa.aux1[4] = (const float*)d_in[14]; pa.bias[4] = (const float*)d_in[15];
    pa.Wx[5] = (const float*)d_in[16]; pa.aux1[5] = (const float*)d_in[17]; pa.bias[5] = (const float*)d_in[18];
    pa.Wx[6] = (const float*)d_in[19]; pa.aux1[6] = (const float*)d_in[20]; pa.bias[6] = (const float*)d_in[21];
    pa.Wx[7] = (const float*)d_in[22]; pa.aux1[7] = (const float*)d_in[24]; pa.aux2[7] = (const float*)d_in[25];
    pa.bias[7] = (const float*)d_in[26];

    const float* Whi = (const float*)d_in[2];
    const float* Whf = (const float*)d_in[5];
    const float* Whc = (const float*)d_in[8];
    const float* Who = (const float*)d_in[23];

    float* out = (float*)d_out;

    cudaFuncSetAttribute(rec_kernel, cudaFuncAttributeMaxDynamicSharedMemorySize,
                         SM_TOTAL);

    init_kernel<<<(BB * HH + 255) / 256, 256>>>();

    dim3 pgrid(HH / 64, (BB * SS) / 64, 8);
    proj_kernel<<<pgrid, 256>>>(pa);

    rec_kernel<<<NBLK, 256, SM_TOTAL>>>(Whi, Whf, Whc, Who, out,
                                        (unsigned long long)out_size);
}